// round 4
// baseline (speedup 1.0000x reference)
#include <cuda_runtime.h>
#include <math.h>

#define N_NODES   100000
#define N_EDGES   1600000
#define E_TOT     (N_EDGES + N_NODES)   // edges + self loops
#define IN_DIM    256
#define HID       64
#define HEADS     3
#define OUTC      (HEADS * HID)         // 192
#define NUM_CLASSES 10
#define NUM_GRAPHS  64

// ---------------- scratch (static device allocations are allowed) ------------
__device__ float g_xl[N_NODES * OUTC];
__device__ float g_xr[N_NODES * OUTC];
__device__ int   g_deg[N_NODES + 1];
__device__ int   g_off[N_NODES + 1];
__device__ int   g_cur[N_NODES];
__device__ int   g_csr[E_TOT];

static __device__ __forceinline__ int clampi(int v, int lo, int hi) {
    return v < lo ? lo : (v > hi ? hi : v);
}

// ---------------- GEMM: y = x @ W + b  (two weight sets in one grid) ---------
// blockIdx.y in [0,6): 0..2 -> W_l cols 0/64/128 ; 3..5 -> W_r cols 0/64/128
__global__ __launch_bounds__(256) void gemm_kernel(
    const float* __restrict__ x,
    const float* __restrict__ Wl, const float* __restrict__ bl,
    const float* __restrict__ Wr, const float* __restrict__ br)
{
    const int cb   = blockIdx.y;
    const float* W = (cb < 3) ? Wl : Wr;
    const float* b = (cb < 3) ? bl : br;
    float* Y       = (cb < 3) ? g_xl : g_xr;
    const int col0 = (cb % 3) * 64;
    const int row0 = blockIdx.x * 128;

    __shared__ float xs[128][17];   // padded to kill bank conflicts
    __shared__ float ws[16][64];

    const int tid = threadIdx.x;
    const int tx  = tid & 15;       // 16 col-groups of 4
    const int ty  = tid >> 4;       // 16 row-groups of 8

    float acc[8][4];
    #pragma unroll
    for (int r = 0; r < 8; r++)
        #pragma unroll
        for (int j = 0; j < 4; j++) acc[r][j] = 0.f;

    for (int k0 = 0; k0 < IN_DIM; k0 += 16) {
        #pragma unroll
        for (int i = 0; i < 8; i++) {
            int r  = ty + 16 * i;
            int gr = row0 + r;
            xs[r][tx] = (gr < N_NODES) ? x[gr * IN_DIM + k0 + tx] : 0.f;
        }
        #pragma unroll
        for (int i = 0; i < 4; i++) {
            int idx = tid + 256 * i;
            int kr = idx >> 6, c = idx & 63;
            ws[kr][c] = W[(k0 + kr) * OUTC + col0 + c];
        }
        __syncthreads();

        #pragma unroll
        for (int kk = 0; kk < 16; kk++) {
            float bv[4];
            #pragma unroll
            for (int j = 0; j < 4; j++) bv[j] = ws[kk][tx * 4 + j];
            #pragma unroll
            for (int r = 0; r < 8; r++) {
                float av = xs[ty * 8 + r][kk];
                #pragma unroll
                for (int j = 0; j < 4; j++)
                    acc[r][j] = fmaf(av, bv[j], acc[r][j]);
            }
        }
        __syncthreads();
    }

    #pragma unroll
    for (int r = 0; r < 8; r++) {
        int gr = row0 + ty * 8 + r;
        if (gr < N_NODES) {
            #pragma unroll
            for (int j = 0; j < 4; j++) {
                int c = col0 + tx * 4 + j;
                Y[gr * OUTC + c] = acc[r][j] + b[c];
            }
        }
    }
}

// ---------------- CSR construction ------------------------------------------
__global__ void deg_init_kernel() {
    int i = blockIdx.x * blockDim.x + threadIdx.x;
    if (i < N_NODES) g_deg[i] = 1;              // self loop
}

__global__ void deg_count_kernel(const int* __restrict__ ei) {
    int e = blockIdx.x * blockDim.x + threadIdx.x;
    if (e < N_EDGES) {
        int d = clampi(ei[N_EDGES + e], 0, N_NODES - 1);
        atomicAdd(&g_deg[d], 1);
    }
}

__global__ __launch_bounds__(1024) void scan_kernel() {
    __shared__ int s[1024];
    __shared__ int carry_s;
    const int tid = threadIdx.x;
    if (tid == 0) carry_s = 0;
    __syncthreads();

    for (int base = 0; base < N_NODES; base += 1024) {
        int idx = base + tid;
        int v   = (idx < N_NODES) ? g_deg[idx] : 0;
        int sum = v;
        #pragma unroll
        for (int off = 1; off < 1024; off <<= 1) {
            s[tid] = sum;
            __syncthreads();
            if (tid >= off) sum += s[tid - off];
            __syncthreads();
        }
        int total_prev = carry_s;
        int excl = total_prev + sum - v;
        if (idx < N_NODES) { g_off[idx] = excl; g_cur[idx] = excl; }
        __syncthreads();
        if (tid == 1023) carry_s = total_prev + sum;
        __syncthreads();
    }
    if (tid == 0) g_off[N_NODES] = E_TOT;
}

__global__ void scatter_kernel(const int* __restrict__ ei) {
    int e = blockIdx.x * blockDim.x + threadIdx.x;
    if (e >= E_TOT) return;
    int s, d;
    if (e < N_EDGES) {
        s = clampi(ei[e], 0, N_NODES - 1);
        d = clampi(ei[N_EDGES + e], 0, N_NODES - 1);
    } else {
        s = d = e - N_EDGES;
    }
    int pos = atomicAdd(&g_cur[d], 1);
    g_csr[pos] = s;
}

// ---------------- GATv2 aggregation: one warp per destination node ----------
// Column mapping: thread lane owns columns c = lane + 32*k, k=0..5.
// Head of column c: h = c/64 = k/2.
__global__ __launch_bounds__(256) void agg_kernel(
    const float* __restrict__ att, const float* __restrict__ bias,
    float* __restrict__ out_fc, float* __restrict__ out_pre)
{
    const int warp = (blockIdx.x * blockDim.x + threadIdx.x) >> 5;
    const int lane = threadIdx.x & 31;
    if (warp >= N_NODES) return;
    const int i = warp;

    float xr_[6], attv[6], acc[6];
    float m[3], dnm[3];
    #pragma unroll
    for (int k = 0; k < 6; k++) {
        xr_[k]  = g_xr[i * OUTC + lane + 32 * k];
        attv[k] = __ldg(&att[lane + 32 * k]);
        acc[k]  = 0.f;
    }
    #pragma unroll
    for (int h = 0; h < 3; h++) { m[h] = -3.0e38f; dnm[h] = 0.f; }

    const int beg = g_off[i], end = g_off[i + 1];
    for (int e = beg; e < end; e++) {
        const int src = g_csr[e];
        float xs_[6];
        float p0 = 0.f, p1 = 0.f, p2 = 0.f;
        #pragma unroll
        for (int k = 0; k < 6; k++) {
            xs_[k] = g_xl[src * OUTC + lane + 32 * k];
            float t = xs_[k] + xr_[k];
            t = (t > 0.f) ? t : 0.2f * t;      // leaky_relu 0.2
            t *= attv[k];
            if (k < 2) p0 += t; else if (k < 4) p1 += t; else p2 += t;
        }
        #pragma unroll
        for (int off = 16; off > 0; off >>= 1) {
            p0 += __shfl_xor_sync(0xffffffffu, p0, off);
            p1 += __shfl_xor_sync(0xffffffffu, p1, off);
            p2 += __shfl_xor_sync(0xffffffffu, p2, off);
        }
        float sc[3] = {p0, p1, p2};
        #pragma unroll
        for (int h = 0; h < 3; h++) {
            float mo = m[h];
            float mn = fmaxf(mo, sc[h]);
            float scale = __expf(mo - mn);
            float w     = __expf(sc[h] - mn);
            dnm[h] = dnm[h] * scale + w;
            acc[2 * h]     = acc[2 * h]     * scale + w * xs_[2 * h];
            acc[2 * h + 1] = acc[2 * h + 1] * scale + w * xs_[2 * h + 1];
            m[h] = mn;
        }
    }

    #pragma unroll
    for (int k = 0; k < 6; k++) {
        int c = lane + 32 * k;
        float o = acc[k] / dnm[k >> 1] + bias[c];
        out_fc[i * OUTC + c] = o;
        out_pre[i * OUTC + c] = (o > 0.f) ? o : 0.01f * o;  // leaky_relu 0.01
    }
}

// ---------------- mean pool per graph (batch is sorted int32) ----------------
__global__ __launch_bounds__(192) void pool_kernel(
    const int* __restrict__ batch,
    const float* __restrict__ pre, float* __restrict__ post)
{
    const int g = blockIdx.x;
    const int c = threadIdx.x;
    __shared__ int sbeg, send;
    if (c < 2) {
        int target = g + c;
        int lo = 0, hi = N_NODES;
        while (lo < hi) {
            int mid = (lo + hi) >> 1;
            if (batch[mid] < target) lo = mid + 1; else hi = mid;
        }
        if (c == 0) sbeg = lo; else send = lo;
    }
    __syncthreads();
    float sum = 0.f;
    for (int r = sbeg; r < send; r++) sum += pre[r * OUTC + c];
    float cnt = (float)(send - sbeg);
    post[g * OUTC + c] = sum / fmaxf(cnt, 1.f);
}

// ---------------- classifier -------------------------------------------------
__global__ void cls_kernel(const float* __restrict__ post,
                           const float* __restrict__ Wc,
                           const float* __restrict__ bc,
                           float* __restrict__ logits)
{
    int t = blockIdx.x * blockDim.x + threadIdx.x;
    if (t >= NUM_GRAPHS * NUM_CLASSES) return;
    int g = t / NUM_CLASSES, c = t % NUM_CLASSES;
    float s = bc[c];
    #pragma unroll 8
    for (int k = 0; k < OUTC; k++)
        s = fmaf(post[g * OUTC + k], Wc[k * NUM_CLASSES + c], s);
    logits[g * NUM_CLASSES + c] = s;
}

// ---------------- launch -----------------------------------------------------
extern "C" void kernel_launch(void* const* d_in, const int* in_sizes, int n_in,
                              void* d_out, int out_size)
{
    const float* x     = (const float*)d_in[0];
    const int*   ei    = (const int*)d_in[1];    // int32! (jax x64 disabled)
    const int*   batch = (const int*)d_in[2];    // int32!
    const float* Wl   = (const float*)d_in[3];
    const float* bl   = (const float*)d_in[4];
    const float* Wr   = (const float*)d_in[5];
    const float* br   = (const float*)d_in[6];
    const float* att  = (const float*)d_in[7];
    const float* bias = (const float*)d_in[8];
    const float* Wc   = (const float*)d_in[9];
    const float* bc   = (const float*)d_in[10];

    float* out        = (float*)d_out;
    float* out_logits = out;                                    // 64*10
    float* out_pre    = out + NUM_GRAPHS * NUM_CLASSES;         // N*192
    float* out_post   = out_pre + (size_t)N_NODES * OUTC;       // 64*192
    float* out_fc     = out_post + NUM_GRAPHS * OUTC;           // N*192

    // 1) node transforms
    gemm_kernel<<<dim3((N_NODES + 127) / 128, 6), 256>>>(x, Wl, bl, Wr, br);

    // 2) CSR (with self loops)
    deg_init_kernel<<<(N_NODES + 255) / 256, 256>>>();
    deg_count_kernel<<<(N_EDGES + 255) / 256, 256>>>(ei);
    scan_kernel<<<1, 1024>>>();
    scatter_kernel<<<(E_TOT + 255) / 256, 256>>>(ei);

    // 3) attention softmax + aggregation, one warp per node
    agg_kernel<<<(N_NODES * 32 + 255) / 256, 256>>>(att, bias, out_fc, out_pre);

    // 4) mean pool + classifier
    pool_kernel<<<NUM_GRAPHS, 192>>>(batch, out_pre, out_post);
    cls_kernel<<<1, NUM_GRAPHS * NUM_CLASSES>>>(out_post, Wc, bc, out_logits);
}

// round 5
// speedup vs baseline: 1.2058x; 1.2058x over previous
#include <cuda_runtime.h>
#include <math.h>

#define N_NODES   100000
#define N_EDGES   1600000
#define E_TOT     (N_EDGES + N_NODES)   // edges + self loops
#define IN_DIM    256
#define HID       64
#define HEADS     3
#define OUTC      (HEADS * HID)         // 192
#define NUM_CLASSES 10
#define NUM_GRAPHS  64

#define SCAN_BLK  1024
#define N_SBLKS   ((N_NODES + SCAN_BLK - 1) / SCAN_BLK)   // 98

// ---------------- scratch ----------------------------------------------------
__device__ float g_xl[N_NODES * OUTC];
__device__ float g_xr[N_NODES * OUTC];
__device__ int   g_deg[N_NODES + 1];
__device__ int   g_off[N_NODES + 1];
__device__ int   g_cur[N_NODES];
__device__ int   g_csr[E_TOT];
__device__ int   g_bsum[N_SBLKS];
__device__ int   g_boff[N_SBLKS];

static __device__ __forceinline__ int clampi(int v, int lo, int hi) {
    return v < lo ? lo : (v > hi ? hi : v);
}

// ---------------- GEMM: y = x @ W + b ---------------------------------------
// Block tile 256 rows x 64 cols, 256 threads, 8x8 micro-tile (split-4 mapping).
// blockIdx.y in [0,6): 0..2 -> W_l cols 0/64/128 ; 3..5 -> W_r.
__global__ __launch_bounds__(256) void gemm_kernel(
    const float* __restrict__ x,
    const float* __restrict__ Wl, const float* __restrict__ bl,
    const float* __restrict__ Wr, const float* __restrict__ br)
{
    const int cb   = blockIdx.y;
    const float* W = (cb < 3) ? Wl : Wr;
    const float* b = (cb < 3) ? bl : br;
    float* Y       = (cb < 3) ? g_xl : g_xr;
    const int col0 = (cb % 3) * 64;
    const int row0 = blockIdx.x * 256;

    __shared__ float xsT[16][256];   // transposed: [k][row]
    __shared__ float ws[16][64];

    const int tid = threadIdx.x;
    const int tx  = tid & 7;         // 8 col groups
    const int ty  = tid >> 3;        // 32 row groups

    // micro-tile: rows {ty*4+r, 128+ty*4+r}, cols {tx*4+j, 32+tx*4+j}
    float acc[8][8];
    #pragma unroll
    for (int r = 0; r < 8; r++)
        #pragma unroll
        for (int j = 0; j < 8; j++) acc[r][j] = 0.f;

    const int  ldrow = row0 + tid;
    const bool rv    = ldrow < N_NODES;
    const float4* x4 = (const float4*)(x + (size_t)ldrow * IN_DIM);

    const int wkr = tid >> 4;            // 0..15
    const int wc  = (tid & 15) * 4;      // 0..60

    for (int k0 = 0; k0 < IN_DIM; k0 += 16) {
        #pragma unroll
        for (int i = 0; i < 4; i++) {
            float4 v = rv ? x4[(k0 >> 2) + i] : make_float4(0.f, 0.f, 0.f, 0.f);
            xsT[4 * i + 0][tid] = v.x;
            xsT[4 * i + 1][tid] = v.y;
            xsT[4 * i + 2][tid] = v.z;
            xsT[4 * i + 3][tid] = v.w;
        }
        {
            float4 w4 = *(const float4*)&W[(size_t)(k0 + wkr) * OUTC + col0 + wc];
            *(float4*)&ws[wkr][wc] = w4;
        }
        __syncthreads();

        #pragma unroll
        for (int kk = 0; kk < 16; kk++) {
            float4 a0 = *(const float4*)&xsT[kk][ty * 4];
            float4 a1 = *(const float4*)&xsT[kk][128 + ty * 4];
            float4 b0 = *(const float4*)&ws[kk][tx * 4];
            float4 b1 = *(const float4*)&ws[kk][32 + tx * 4];
            float a[8] = {a0.x, a0.y, a0.z, a0.w, a1.x, a1.y, a1.z, a1.w};
            float bb[8] = {b0.x, b0.y, b0.z, b0.w, b1.x, b1.y, b1.z, b1.w};
            #pragma unroll
            for (int r = 0; r < 8; r++)
                #pragma unroll
                for (int j = 0; j < 8; j++)
                    acc[r][j] = fmaf(a[r], bb[j], acc[r][j]);
        }
        __syncthreads();
    }

    float bv[8];
    #pragma unroll
    for (int j = 0; j < 4; j++) {
        bv[j]     = b[col0 + tx * 4 + j];
        bv[j + 4] = b[col0 + 32 + tx * 4 + j];
    }

    #pragma unroll
    for (int half = 0; half < 2; half++) {
        #pragma unroll
        for (int r = 0; r < 4; r++) {
            int gr = row0 + half * 128 + ty * 4 + r;
            if (gr < N_NODES) {
                float* yp = Y + (size_t)gr * OUTC + col0;
                float4 o0, o1;
                o0.x = acc[half * 4 + r][0] + bv[0];
                o0.y = acc[half * 4 + r][1] + bv[1];
                o0.z = acc[half * 4 + r][2] + bv[2];
                o0.w = acc[half * 4 + r][3] + bv[3];
                o1.x = acc[half * 4 + r][4] + bv[4];
                o1.y = acc[half * 4 + r][5] + bv[5];
                o1.z = acc[half * 4 + r][6] + bv[6];
                o1.w = acc[half * 4 + r][7] + bv[7];
                *(float4*)(yp + tx * 4)      = o0;
                *(float4*)(yp + 32 + tx * 4) = o1;
            }
        }
    }
}

// ---------------- CSR construction ------------------------------------------
__global__ void deg_init_kernel() {
    int i = blockIdx.x * blockDim.x + threadIdx.x;
    if (i < N_NODES) g_deg[i] = 1;              // self loop
}

__global__ void deg_count_kernel(const int* __restrict__ ei) {
    int e = blockIdx.x * blockDim.x + threadIdx.x;
    if (e < N_EDGES) {
        int d = clampi(ei[N_EDGES + e], 0, N_NODES - 1);
        atomicAdd(&g_deg[d], 1);
    }
}

// phase 1: per-block exclusive scan, emit block sums
__global__ __launch_bounds__(SCAN_BLK) void scan_local_kernel() {
    __shared__ int s[SCAN_BLK];
    const int tid = threadIdx.x;
    const int idx = blockIdx.x * SCAN_BLK + tid;
    int v = (idx < N_NODES) ? g_deg[idx] : 0;
    int sum = v;
    #pragma unroll
    for (int off = 1; off < SCAN_BLK; off <<= 1) {
        s[tid] = sum;
        __syncthreads();
        if (tid >= off) sum += s[tid - off];
        __syncthreads();
    }
    if (idx < N_NODES) g_off[idx] = sum - v;      // exclusive, block-local
    if (tid == SCAN_BLK - 1) g_bsum[blockIdx.x] = sum;
}

// phase 2: scan the 98 block sums (1 block)
__global__ __launch_bounds__(128) void scan_bsum_kernel() {
    __shared__ int s[128];
    const int tid = threadIdx.x;
    int v = (tid < N_SBLKS) ? g_bsum[tid] : 0;
    int sum = v;
    #pragma unroll
    for (int off = 1; off < 128; off <<= 1) {
        s[tid] = sum;
        __syncthreads();
        if (tid >= off) sum += s[tid - off];
        __syncthreads();
    }
    if (tid < N_SBLKS) g_boff[tid] = sum - v;     // exclusive
}

// phase 3: add block offsets
__global__ __launch_bounds__(SCAN_BLK) void scan_add_kernel() {
    const int idx = blockIdx.x * SCAN_BLK + threadIdx.x;
    if (idx < N_NODES) {
        int o = g_off[idx] + g_boff[blockIdx.x];
        g_off[idx] = o;
        g_cur[idx] = o;
    }
    if (idx == 0) g_off[N_NODES] = E_TOT;
}

__global__ void scatter_kernel(const int* __restrict__ ei) {
    int e = blockIdx.x * blockDim.x + threadIdx.x;
    if (e >= E_TOT) return;
    int s, d;
    if (e < N_EDGES) {
        s = clampi(ei[e], 0, N_NODES - 1);
        d = clampi(ei[N_EDGES + e], 0, N_NODES - 1);
    } else {
        s = d = e - N_EDGES;
    }
    int pos = atomicAdd(&g_cur[d], 1);
    g_csr[pos] = s;
}

// ---------------- GATv2 aggregation: one warp per destination node ----------
__global__ __launch_bounds__(256) void agg_kernel(
    const float* __restrict__ att, const float* __restrict__ bias,
    float* __restrict__ out_fc, float* __restrict__ out_pre)
{
    const int warp = (blockIdx.x * blockDim.x + threadIdx.x) >> 5;
    const int lane = threadIdx.x & 31;
    if (warp >= N_NODES) return;
    const int i = warp;

    float xr_[6], attv[6], acc[6];
    float m[3], dnm[3];
    #pragma unroll
    for (int k = 0; k < 6; k++) {
        xr_[k]  = g_xr[i * OUTC + lane + 32 * k];
        attv[k] = __ldg(&att[lane + 32 * k]);
        acc[k]  = 0.f;
    }
    #pragma unroll
    for (int h = 0; h < 3; h++) { m[h] = -3.0e38f; dnm[h] = 0.f; }

    const int beg = g_off[i], end = g_off[i + 1];
    for (int e = beg; e < end; e++) {
        const int src = g_csr[e];
        float xs_[6];
        float p0 = 0.f, p1 = 0.f, p2 = 0.f;
        #pragma unroll
        for (int k = 0; k < 6; k++) {
            xs_[k] = g_xl[src * OUTC + lane + 32 * k];
            float t = xs_[k] + xr_[k];
            t = (t > 0.f) ? t : 0.2f * t;      // leaky_relu 0.2
            t *= attv[k];
            if (k < 2) p0 += t; else if (k < 4) p1 += t; else p2 += t;
        }
        #pragma unroll
        for (int off = 16; off > 0; off >>= 1) {
            p0 += __shfl_xor_sync(0xffffffffu, p0, off);
            p1 += __shfl_xor_sync(0xffffffffu, p1, off);
            p2 += __shfl_xor_sync(0xffffffffu, p2, off);
        }
        float sc[3] = {p0, p1, p2};
        #pragma unroll
        for (int h = 0; h < 3; h++) {
            float mo = m[h];
            float mn = fmaxf(mo, sc[h]);
            float scale = __expf(mo - mn);
            float w     = __expf(sc[h] - mn);
            dnm[h] = dnm[h] * scale + w;
            acc[2 * h]     = acc[2 * h]     * scale + w * xs_[2 * h];
            acc[2 * h + 1] = acc[2 * h + 1] * scale + w * xs_[2 * h + 1];
            m[h] = mn;
        }
    }

    #pragma unroll
    for (int k = 0; k < 6; k++) {
        int c = lane + 32 * k;
        float o = acc[k] / dnm[k >> 1] + bias[c];
        out_fc[i * OUTC + c] = o;
        out_pre[i * OUTC + c] = (o > 0.f) ? o : 0.01f * o;  // leaky_relu 0.01
    }
}

// ---------------- mean pool per graph (batch sorted int32) -------------------
__global__ __launch_bounds__(192) void pool_kernel(
    const int* __restrict__ batch,
    const float* __restrict__ pre, float* __restrict__ post)
{
    const int g = blockIdx.x;
    const int c = threadIdx.x;
    __shared__ int sbeg, send;
    if (c < 2) {
        int target = g + c;
        int lo = 0, hi = N_NODES;
        while (lo < hi) {
            int mid = (lo + hi) >> 1;
            if (batch[mid] < target) lo = mid + 1; else hi = mid;
        }
        if (c == 0) sbeg = lo; else send = lo;
    }
    __syncthreads();
    float sum = 0.f;
    for (int r = sbeg; r < send; r++) sum += pre[r * OUTC + c];
    float cnt = (float)(send - sbeg);
    post[g * OUTC + c] = sum / fmaxf(cnt, 1.f);
}

// ---------------- classifier -------------------------------------------------
__global__ void cls_kernel(const float* __restrict__ post,
                           const float* __restrict__ Wc,
                           const float* __restrict__ bc,
                           float* __restrict__ logits)
{
    int t = blockIdx.x * blockDim.x + threadIdx.x;
    if (t >= NUM_GRAPHS * NUM_CLASSES) return;
    int g = t / NUM_CLASSES, c = t % NUM_CLASSES;
    float s = bc[c];
    #pragma unroll 8
    for (int k = 0; k < OUTC; k++)
        s = fmaf(post[g * OUTC + k], Wc[k * NUM_CLASSES + c], s);
    logits[g * NUM_CLASSES + c] = s;
}

// ---------------- launch -----------------------------------------------------
extern "C" void kernel_launch(void* const* d_in, const int* in_sizes, int n_in,
                              void* d_out, int out_size)
{
    const float* x     = (const float*)d_in[0];
    const int*   ei    = (const int*)d_in[1];    // int32 (jax x64 disabled)
    const int*   batch = (const int*)d_in[2];    // int32
    const float* Wl   = (const float*)d_in[3];
    const float* bl   = (const float*)d_in[4];
    const float* Wr   = (const float*)d_in[5];
    const float* br   = (const float*)d_in[6];
    const float* att  = (const float*)d_in[7];
    const float* bias = (const float*)d_in[8];
    const float* Wc   = (const float*)d_in[9];
    const float* bc   = (const float*)d_in[10];

    float* out        = (float*)d_out;
    float* out_logits = out;                                    // 64*10
    float* out_pre    = out + NUM_GRAPHS * NUM_CLASSES;         // N*192
    float* out_post   = out_pre + (size_t)N_NODES * OUTC;       // 64*192
    float* out_fc     = out_post + NUM_GRAPHS * OUTC;           // N*192

    // 1) node transforms (256-row tiles, 6 column blocks)
    gemm_kernel<<<dim3((N_NODES + 255) / 256, 6), 256>>>(x, Wl, bl, Wr, br);

    // 2) CSR (with self loops) — parallel 3-phase scan
    deg_init_kernel<<<(N_NODES + 255) / 256, 256>>>();
    deg_count_kernel<<<(N_EDGES + 255) / 256, 256>>>(ei);
    scan_local_kernel<<<N_SBLKS, SCAN_BLK>>>();
    scan_bsum_kernel<<<1, 128>>>();
    scan_add_kernel<<<N_SBLKS, SCAN_BLK>>>();
    scatter_kernel<<<(E_TOT + 255) / 256, 256>>>(ei);

    // 3) attention softmax + aggregation, one warp per node
    agg_kernel<<<(N_NODES * 32 + 255) / 256, 256>>>(att, bias, out_fc, out_pre);

    // 4) mean pool + classifier
    pool_kernel<<<NUM_GRAPHS, 192>>>(batch, out_pre, out_post);
    cls_kernel<<<1, NUM_GRAPHS * NUM_CLASSES>>>(out_post, Wc, bc, out_logits);
}

// round 7
// speedup vs baseline: 1.5111x; 1.2532x over previous
#include <cuda_runtime.h>
#include <cuda_bf16.h>
#include <cstdint>
#include <math.h>

#define N_NODES   100000
#define N_EDGES   1600000
#define E_TOT     (N_EDGES + N_NODES)
#define IN_DIM    256
#define HID       64
#define HEADS     3
#define OUTC      (HEADS * HID)         // 192
#define NUM_CLASSES 10
#define NUM_GRAPHS  64

#define SCAN_BLK  1024
#define N_SBLKS   ((N_NODES + SCAN_BLK - 1) / SCAN_BLK)   // 98

#define M_TILE    128
#define N_TILES_M 782                   // ceil(100000/128)
#define ROWS_PAD  (N_TILES_M * M_TILE)  // 100096

// ---------------- scratch ----------------------------------------------------
__device__ float g_xl[N_NODES * OUTC];
__device__ float g_xr[N_NODES * OUTC];
__device__ int   g_deg[N_NODES + 1];
__device__ int   g_off[N_NODES + 1];
__device__ int   g_cur[N_NODES];
__device__ int   g_csr[E_TOT];
__device__ int   g_bsum[N_SBLKS];
__device__ int   g_boff[N_SBLKS];
// decomposed operands: packed bf16 pairs (k, k+1) as uint32 words
__device__ __align__(16) unsigned g_ahw[ROWS_PAD * (IN_DIM / 2)];       // hi(x)
__device__ __align__(16) unsigned g_alw[ROWS_PAD * (IN_DIM / 2)];       // lo(x)
__device__ __align__(16) unsigned g_bhw[2 * OUTC * (IN_DIM / 2)];       // hi(W^T)
__device__ __align__(16) unsigned g_blw[2 * OUTC * (IN_DIM / 2)];       // lo(W^T)

static __device__ __forceinline__ int clampi(int v, int lo, int hi) {
    return v < lo ? lo : (v > hi ? hi : v);
}

static __device__ __forceinline__ unsigned pack_bf16(unsigned short a, unsigned short b) {
    return (unsigned)a | ((unsigned)b << 16);
}

static __device__ __forceinline__ void split_bf16(float f, unsigned short& h, unsigned short& l) {
    __nv_bfloat16 hb = __float2bfloat16(f);
    __nv_bfloat16 lb = __float2bfloat16(f - __bfloat162float(hb));
    h = __bfloat16_as_ushort(hb);
    l = __bfloat16_as_ushort(lb);
}

// ---------------- prep A: x -> hi/lo bf16 packed row-major -------------------
__global__ __launch_bounds__(256) void prep_a_kernel(const float* __restrict__ x)
{
    int t = blockIdx.x * blockDim.x + threadIdx.x;
    if (t >= ROWS_PAD * 64) return;
    int k4  = t & 63;                    // float4 index within row
    int row = t >> 6;
    float4 v = make_float4(0.f, 0.f, 0.f, 0.f);
    if (row < N_NODES) v = *(const float4*)(x + (size_t)row * IN_DIM + k4 * 4);
    float f[4] = {v.x, v.y, v.z, v.w};
    unsigned short h[4], l[4];
    #pragma unroll
    for (int j = 0; j < 4; j++) split_bf16(f[j], h[j], l[j]);
    int base = row * (IN_DIM / 2) + k4 * 2;
    g_ahw[base]     = pack_bf16(h[0], h[1]);
    g_ahw[base + 1] = pack_bf16(h[2], h[3]);
    g_alw[base]     = pack_bf16(l[0], l[1]);
    g_alw[base + 1] = pack_bf16(l[2], l[3]);
}

// ---------------- prep B: W[k][n] -> B^T[n][k] hi/lo bf16 packed -------------
__global__ __launch_bounds__(256) void prep_b_kernel(
    const float* __restrict__ Wl, const float* __restrict__ Wr)
{
    int t = blockIdx.x * blockDim.x + threadIdx.x;
    if (t >= 2 * OUTC * 64) return;      // sets x n x k-quads
    int k4 = t & 63;
    int n  = (t >> 6) % OUTC;
    int s  = t / (OUTC * 64);
    const float* W = s ? Wr : Wl;
    float f[4];
    #pragma unroll
    for (int j = 0; j < 4; j++) f[j] = W[(size_t)(k4 * 4 + j) * OUTC + n];
    unsigned short h[4], l[4];
    #pragma unroll
    for (int j = 0; j < 4; j++) split_bf16(f[j], h[j], l[j]);
    int base = (s * OUTC + n) * (IN_DIM / 2) + k4 * 2;
    g_bhw[base]     = pack_bf16(h[0], h[1]);
    g_bhw[base + 1] = pack_bf16(h[2], h[3]);
    g_blw[base]     = pack_bf16(l[0], l[1]);
    g_blw[base + 1] = pack_bf16(l[2], l[3]);
}

// ---------------- HMMA GEMM: y = x @ W + b (bf16x3 split) --------------------
// grid (782, 6): blockIdx.y = set*3 + nb. Block 128 rows x 64 cols, 8 warps,
// warp tile 32x32 = 2x4 m16n8k16 mma tiles. K chunks of 32.
#define KCH    32
#define KW     (KCH / 2)                 // 16 words per row per chunk
#define PADW   20                        // padded row stride in words (40 bf16)

static __device__ __forceinline__ void mma_bf16(
    float& c0, float& c1, float& c2, float& c3,
    unsigned a0, unsigned a1, unsigned a2, unsigned a3,
    unsigned b0, unsigned b1)
{
    asm volatile(
        "mma.sync.aligned.m16n8k16.row.col.f32.bf16.bf16.f32 "
        "{%0,%1,%2,%3}, {%4,%5,%6,%7}, {%8,%9}, {%0,%1,%2,%3};"
        : "+f"(c0), "+f"(c1), "+f"(c2), "+f"(c3)
        : "r"(a0), "r"(a1), "r"(a2), "r"(a3), "r"(b0), "r"(b1));
}

__global__ __launch_bounds__(256) void mma_gemm_kernel(
    const float* __restrict__ bl, const float* __restrict__ br)
{
    __shared__ unsigned sAh[128 * PADW];
    __shared__ unsigned sAl[128 * PADW];
    __shared__ unsigned sBh[64 * PADW];
    __shared__ unsigned sBl[64 * PADW];

    const int tid  = threadIdx.x;
    const int wid  = tid >> 5;
    const int lane = tid & 31;
    const int tile = blockIdx.x;
    const int set  = blockIdx.y / 3;
    const int nb   = blockIdx.y % 3;
    const int row0 = tile * M_TILE;
    const int col0 = nb * 64;
    float* Y        = set ? g_xr : g_xl;
    const float* bv = set ? br : bl;

    const int warp_m = (wid & 3) * 32;
    const int warp_n = (wid >> 2) * 32;
    const int lq = lane >> 2;            // lane/4
    const int lr = lane & 3;             // lane%4

    float acc[2][4][4];
    #pragma unroll
    for (int mi = 0; mi < 2; mi++)
        #pragma unroll
        for (int ni = 0; ni < 4; ni++)
            #pragma unroll
            for (int q = 0; q < 4; q++) acc[mi][ni][q] = 0.f;

    #pragma unroll 1
    for (int ch = 0; ch < IN_DIM / KCH; ch++) {
        const int k0w = ch * KW;
        // fill A (128x16 words x2) and B (64x16 words x2), padded stride
        #pragma unroll
        for (int i = 0; i < 8; i++) {
            int t = tid + 256 * i;
            int r = t >> 4, kw = t & 15;
            int src = (row0 + r) * (IN_DIM / 2) + k0w + kw;
            sAh[r * PADW + kw] = g_ahw[src];
            sAl[r * PADW + kw] = g_alw[src];
        }
        #pragma unroll
        for (int i = 0; i < 4; i++) {
            int t = tid + 256 * i;
            int r = t >> 4, kw = t & 15;
            int src = (set * OUTC + col0 + r) * (IN_DIM / 2) + k0w + kw;
            sBh[r * PADW + kw] = g_bhw[src];
            sBl[r * PADW + kw] = g_blw[src];
        }
        __syncthreads();

        #pragma unroll
        for (int ks = 0; ks < 2; ks++) {
            unsigned ah[2][4], al[2][4], bh[4][2], blo[4][2];
            #pragma unroll
            for (int mi = 0; mi < 2; mi++) {
                int r = warp_m + mi * 16 + lq;
                int w = r * PADW + ks * 8 + lr;
                ah[mi][0] = sAh[w];            ah[mi][1] = sAh[w + 8 * PADW];
                ah[mi][2] = sAh[w + 4];        ah[mi][3] = sAh[w + 8 * PADW + 4];
                al[mi][0] = sAl[w];            al[mi][1] = sAl[w + 8 * PADW];
                al[mi][2] = sAl[w + 4];        al[mi][3] = sAl[w + 8 * PADW + 4];
            }
            #pragma unroll
            for (int ni = 0; ni < 4; ni++) {
                int n = warp_n + ni * 8 + lq;
                int w = n * PADW + ks * 8 + lr;
                bh[ni][0] = sBh[w];  bh[ni][1] = sBh[w + 4];
                blo[ni][0] = sBl[w]; blo[ni][1] = sBl[w + 4];
            }
            #pragma unroll
            for (int mi = 0; mi < 2; mi++)
                #pragma unroll
                for (int ni = 0; ni < 4; ni++) {
                    float* c = acc[mi][ni];
                    mma_bf16(c[0], c[1], c[2], c[3],
                             ah[mi][0], ah[mi][1], ah[mi][2], ah[mi][3],
                             bh[ni][0], bh[ni][1]);
                    mma_bf16(c[0], c[1], c[2], c[3],
                             ah[mi][0], ah[mi][1], ah[mi][2], ah[mi][3],
                             blo[ni][0], blo[ni][1]);
                    mma_bf16(c[0], c[1], c[2], c[3],
                             al[mi][0], al[mi][1], al[mi][2], al[mi][3],
                             bh[ni][0], bh[ni][1]);
                }
        }
        __syncthreads();
    }

    // epilogue: c0,c1 -> (row, col..col+1); c2,c3 -> (row+8, ...)
    #pragma unroll
    for (int ni = 0; ni < 4; ni++) {
        int c = col0 + warp_n + ni * 8 + lr * 2;
        float b0 = bv[c], b1 = bv[c + 1];
        #pragma unroll
        for (int mi = 0; mi < 2; mi++) {
            int r_lo = row0 + warp_m + mi * 16 + lq;
            int r_hi = r_lo + 8;
            float* ac = acc[mi][ni];
            if (r_lo < N_NODES) {
                float2 o = make_float2(ac[0] + b0, ac[1] + b1);
                *(float2*)(Y + (size_t)r_lo * OUTC + c) = o;
            }
            if (r_hi < N_NODES) {
                float2 o = make_float2(ac[2] + b0, ac[3] + b1);
                *(float2*)(Y + (size_t)r_hi * OUTC + c) = o;
            }
        }
    }
}

// ---------------- CSR construction ------------------------------------------
__global__ void deg_init_kernel() {
    int i = blockIdx.x * blockDim.x + threadIdx.x;
    if (i < N_NODES) g_deg[i] = 1;
}

__global__ void deg_count_kernel(const int* __restrict__ ei) {
    int e = blockIdx.x * blockDim.x + threadIdx.x;
    if (e < N_EDGES) {
        int d = clampi(ei[N_EDGES + e], 0, N_NODES - 1);
        atomicAdd(&g_deg[d], 1);
    }
}

__global__ __launch_bounds__(SCAN_BLK) void scan_local_kernel() {
    __shared__ int s[SCAN_BLK];
    const int tid = threadIdx.x;
    const int idx = blockIdx.x * SCAN_BLK + tid;
    int v = (idx < N_NODES) ? g_deg[idx] : 0;
    int sum = v;
    #pragma unroll
    for (int off = 1; off < SCAN_BLK; off <<= 1) {
        s[tid] = sum;
        __syncthreads();
        if (tid >= off) sum += s[tid - off];
        __syncthreads();
    }
    if (idx < N_NODES) g_off[idx] = sum - v;
    if (tid == SCAN_BLK - 1) g_bsum[blockIdx.x] = sum;
}

__global__ __launch_bounds__(128) void scan_bsum_kernel() {
    __shared__ int s[128];
    const int tid = threadIdx.x;
    int v = (tid < N_SBLKS) ? g_bsum[tid] : 0;
    int sum = v;
    #pragma unroll
    for (int off = 1; off < 128; off <<= 1) {
        s[tid] = sum;
        __syncthreads();
        if (tid >= off) sum += s[tid - off];
        __syncthreads();
    }
    if (tid < N_SBLKS) g_boff[tid] = sum - v;
}

__global__ __launch_bounds__(SCAN_BLK) void scan_add_kernel() {
    const int idx = blockIdx.x * SCAN_BLK + threadIdx.x;
    if (idx < N_NODES) {
        int o = g_off[idx] + g_boff[blockIdx.x];
        g_off[idx] = o;
        g_cur[idx] = o;
    }
    if (idx == 0) g_off[N_NODES] = E_TOT;
}

__global__ void scatter_kernel(const int* __restrict__ ei) {
    int e = blockIdx.x * blockDim.x + threadIdx.x;
    if (e >= E_TOT) return;
    int s, d;
    if (e < N_EDGES) {
        s = clampi(ei[e], 0, N_NODES - 1);
        d = clampi(ei[N_EDGES + e], 0, N_NODES - 1);
    } else {
        s = d = e - N_EDGES;
    }
    int pos = atomicAdd(&g_cur[d], 1);
    g_csr[pos] = s;
}

// ---------------- GATv2 aggregation: one warp per destination node ----------
__global__ __launch_bounds__(256) void agg_kernel(
    const float* __restrict__ att, const float* __restrict__ bias,
    float* __restrict__ out_fc, float* __restrict__ out_pre)
{
    const int warp = (blockIdx.x * blockDim.x + threadIdx.x) >> 5;
    const int lane = threadIdx.x & 31;
    if (warp >= N_NODES) return;
    const int i = warp;

    float xr_[6], attv[6], acc[6];
    float m[3], dnm[3];
    #pragma unroll
    for (int k = 0; k < 6; k++) {
        xr_[k]  = g_xr[i * OUTC + lane + 32 * k];
        attv[k] = __ldg(&att[lane + 32 * k]);
        acc[k]  = 0.f;
    }
    #pragma unroll
    for (int h = 0; h < 3; h++) { m[h] = -3.0e38f; dnm[h] = 0.f; }

    const int beg = g_off[i], end = g_off[i + 1];
    for (int e = beg; e < end; e++) {
        const int src = g_csr[e];
        float xs_[6];
        float p0 = 0.f, p1 = 0.f, p2 = 0.f;
        #pragma unroll
        for (int k = 0; k < 6; k++) {
            xs_[k] = g_xl[src * OUTC + lane + 32 * k];
            float t = xs_[k] + xr_[k];
            t = (t > 0.f) ? t : 0.2f * t;
            t *= attv[k];
            if (k < 2) p0 += t; else if (k < 4) p1 += t; else p2 += t;
        }
        #pragma unroll
        for (int off = 16; off > 0; off >>= 1) {
            p0 += __shfl_xor_sync(0xffffffffu, p0, off);
            p1 += __shfl_xor_sync(0xffffffffu, p1, off);
            p2 += __shfl_xor_sync(0xffffffffu, p2, off);
        }
        float sc[3] = {p0, p1, p2};
        #pragma unroll
        for (int h = 0; h < 3; h++) {
            float mo = m[h];
            float mn = fmaxf(mo, sc[h]);
            float scale = __expf(mo - mn);
            float w     = __expf(sc[h] - mn);
            dnm[h] = dnm[h] * scale + w;
            acc[2 * h]     = acc[2 * h]     * scale + w * xs_[2 * h];
            acc[2 * h + 1] = acc[2 * h + 1] * scale + w * xs_[2 * h + 1];
            m[h] = mn;
        }
    }

    #pragma unroll
    for (int k = 0; k < 6; k++) {
        int c = lane + 32 * k;
        float o = acc[k] / dnm[k >> 1] + bias[c];
        out_fc[i * OUTC + c] = o;
        out_pre[i * OUTC + c] = (o > 0.f) ? o : 0.01f * o;
    }
}

// ---------------- mean pool per graph (batch sorted int32) -------------------
__global__ __launch_bounds__(192) void pool_kernel(
    const int* __restrict__ batch,
    const float* __restrict__ pre, float* __restrict__ post)
{
    const int g = blockIdx.x;
    const int c = threadIdx.x;
    __shared__ int sbeg, send;
    if (c < 2) {
        int target = g + c;
        int lo = 0, hi = N_NODES;
        while (lo < hi) {
            int mid = (lo + hi) >> 1;
            if (batch[mid] < target) lo = mid + 1; else hi = mid;
        }
        if (c == 0) sbeg = lo; else send = lo;
    }
    __syncthreads();
    float sum = 0.f;
    for (int r = sbeg; r < send; r++) sum += pre[r * OUTC + c];
    float cnt = (float)(send - sbeg);
    post[g * OUTC + c] = sum / fmaxf(cnt, 1.f);
}

// ---------------- classifier -------------------------------------------------
__global__ void cls_kernel(const float* __restrict__ post,
                           const float* __restrict__ Wc,
                           const float* __restrict__ bc,
                           float* __restrict__ logits)
{
    int t = blockIdx.x * blockDim.x + threadIdx.x;
    if (t >= NUM_GRAPHS * NUM_CLASSES) return;
    int g = t / NUM_CLASSES, c = t % NUM_CLASSES;
    float s = bc[c];
    #pragma unroll 8
    for (int k = 0; k < OUTC; k++)
        s = fmaf(post[g * OUTC + k], Wc[k * NUM_CLASSES + c], s);
    logits[g * NUM_CLASSES + c] = s;
}

// ---------------- launch -----------------------------------------------------
extern "C" void kernel_launch(void* const* d_in, const int* in_sizes, int n_in,
                              void* d_out, int out_size)
{
    const float* x     = (const float*)d_in[0];
    const int*   ei    = (const int*)d_in[1];
    const int*   batch = (const int*)d_in[2];
    const float* Wl   = (const float*)d_in[3];
    const float* bl   = (const float*)d_in[4];
    const float* Wr   = (const float*)d_in[5];
    const float* br   = (const float*)d_in[6];
    const float* att  = (const float*)d_in[7];
    const float* bias = (const float*)d_in[8];
    const float* Wc   = (const float*)d_in[9];
    const float* bc   = (const float*)d_in[10];

    float* out        = (float*)d_out;
    float* out_logits = out;
    float* out_pre    = out + NUM_GRAPHS * NUM_CLASSES;
    float* out_post   = out_pre + (size_t)N_NODES * OUTC;
    float* out_fc     = out_post + NUM_GRAPHS * OUTC;

    // 1-2: operand decomposition to bf16 hi/lo
    prep_a_kernel<<<(ROWS_PAD * 64 + 255) / 256, 256>>>(x);
    prep_b_kernel<<<(2 * OUTC * 64 + 255) / 256, 256>>>(Wl, Wr);
    // 3: CSR init (independent)
    deg_init_kernel<<<(N_NODES + 255) / 256, 256>>>();
    // 4: tensor-core GEMM (HMMA mma.sync, bf16x3)
    mma_gemm_kernel<<<dim3(N_TILES_M, 6), 256>>>(bl, br);
    // 5+: CSR build
    deg_count_kernel<<<(N_EDGES + 255) / 256, 256>>>(ei);
    scan_local_kernel<<<N_SBLKS, SCAN_BLK>>>();
    scan_bsum_kernel<<<1, 128>>>();
    scan_add_kernel<<<N_SBLKS, SCAN_BLK>>>();
    scatter_kernel<<<(E_TOT + 255) / 256, 256>>>(ei);
    // aggregation
    agg_kernel<<<(N_NODES * 32 + 255) / 256, 256>>>(att, bias, out_fc, out_pre);
    // pool + classifier
    pool_kernel<<<NUM_GRAPHS, 192>>>(batch, out_pre, out_post);
    cls_kernel<<<1, NUM_GRAPHS * NUM_CLASSES>>>(out_post, Wc, bc, out_logits);
}